// round 3
// baseline (speedup 1.0000x reference)
#include <cuda_runtime.h>
#include <cstdint>
#include <cstddef>

#define BB   8192
#define NN   32
#define DD   128
#define NAE  45   // 3*15 ally entries
#define NOE  48   // 3*16 opp entries

// ---------------- device scratch (no allocations allowed) ----------------
__device__ float g_vu[12 * 128];            // 9 v-vectors (W_i @ a_top_j) then 3 u-vectors (W_j @ a_bot_j)
__device__ float g_z[(size_t)BB * 384];     // per-batch folded features z[b][t*128+d]
__device__ int   g_mask_kind;               // 0=i32 1=u8 2=f32 3=i64 4=f64

// ---------------- mask dtype handling ----------------
__device__ __forceinline__ float mask_val(const void* m, int kind, int idx) {
    switch (kind) {
        case 0:  return (float)((const int*)m)[idx];
        case 1:  return (float)((const unsigned char*)m)[idx];
        case 2:  return ((const float*)m)[idx];
        case 3:  return ((const long long*)m)[idx] ? 1.f : 0.f;
        default: return (((const double*)m)[idx] != 0.0) ? 1.f : 0.f;
    }
}

__global__ void detect_kernel(const unsigned* __restrict__ m) {
    // Scan first 8KB (always in-bounds: mask >= 786432 bytes even as u8).
    int tid = threadIdx.x;
    bool okI = true, okF = true, okD = true, oddNZ = false;
    for (int i = tid * 8; i < tid * 8 + 8; i++) {
        unsigned w = m[i];
        if (w && w != 1u)          okI = false;
        if (w && w != 0x3F800000u) okF = false;
        if (i & 1) {
            if (w) oddNZ = true;
            if (w && w != 0x3FF00000u) okD = false;
        } else {
            if (w) okD = false;
        }
    }
    int aI = __syncthreads_and((int)okI);
    int aF = __syncthreads_and((int)okF);
    int aD = __syncthreads_and((int)okD);
    int oN = __syncthreads_or((int)oddNZ);
    if (tid == 0) {
        int k;
        if (aI)      k = oN ? 0 : 3;   // all words in {0,1}: i32 (odd words carry data) vs i64
        else if (aF) k = 2;            // f32 0.0 / 1.0
        else if (aD) k = 4;            // f64 0.0 / 1.0
        else         k = 1;            // bytes
        g_mask_kind = k;
    }
}

// ---------------- precompute v = W_i @ a_top_j, u = W_j @ a_bot_j ----------------
__global__ void pre_kernel(const float* __restrict__ W, const float* __restrict__ a) {
    int o = blockIdx.x * 256 + threadIdx.x;
    if (o >= 1536) return;
    int vec = o >> 7, d = o & 127;
    const float* wrow;
    const float* av;
    if (vec < 9) { int i = vec / 3, j = vec % 3; wrow = W + i * 16384 + d * 128; av = a + j * 256; }
    else         { int j = vec - 9;              wrow = W + j * 16384 + d * 128; av = a + j * 256 + 128; }
    float s = 0.f;
#pragma unroll 8
    for (int hh = 0; hh < 128; hh++) s += wrow[hh] * av[hh];
    g_vu[o] = s;
}

// ---------------- main: stream h, compute attention coefficients, fold to z ----------------
__global__ void __launch_bounds__(256) main_kernel(const float* __restrict__ h,
                                                   const void* __restrict__ mask) {
    __shared__ __align__(16) float shh[2][NN * DD];   // double-buffered h tile (2 x 16KB)
    __shared__ __align__(16) float svu[1536];
    __shared__ float sp[9];          // p[i*3+j] = h_self . v[i,j]
    __shared__ float ss[3][32];      // s[j][node] = h_node . u[j]  (node 1..31)
    __shared__ float sc[3][32];      // coefficients c[t][node]

    const int tid = threadIdx.x, lane = tid & 31, w = tid >> 5;
    const int kind = g_mask_kind;
    const int b0 = blockIdx.x * 16;

    auto prefetch = [&](int b, int buf) {
        const char* src = (const char*)h + (size_t)b * (NN * DD * 4);
        unsigned smem = (unsigned)__cvta_generic_to_shared(&shh[buf][0]);
#pragma unroll
        for (int k = 0; k < 4; k++) {
            int idx = tid + k * 256;
            asm volatile("cp.async.cg.shared.global [%0], [%1], 16;"
                         :: "r"(smem + idx * 16), "l"(src + idx * 16));
        }
    };

    prefetch(b0, 0);
    asm volatile("cp.async.commit_group;");
    for (int i2 = tid; i2 < 1536; i2 += 256) svu[i2] = g_vu[i2];

    for (int it = 0; it < 16; it++) {
        const int b = b0 + it;
        if (it + 1 < 16) prefetch(b0 + it + 1, (it + 1) & 1);
        asm volatile("cp.async.commit_group;");
        asm volatile("cp.async.wait_group 1;");
        __syncthreads();
        const float* hb = shh[it & 1];

        // ---- 102 warp dots: 9 p (self x a_top) + 93 s (neighbors x a_bot) ----
        for (int id = w; id < 102; id += 8) {
            int row, voff, j = 0, node = 0;
            if (id < 9) { row = 0; voff = id * 128; }
            else { int k = id - 9; j = k / 31; node = 1 + (k % 31); row = node; voff = 1152 + j * 128; }
            float4 hv = *(const float4*)&hb[row * 128 + lane * 4];
            float4 vv = *(const float4*)&svu[voff + lane * 4];
            float d4 = hv.x * vv.x + hv.y * vv.y + hv.z * vv.z + hv.w * vv.w;
#pragma unroll
            for (int o = 16; o; o >>= 1) d4 += __shfl_xor_sync(0xffffffffu, d4, o);
            if (lane == 0) { if (id < 9) sp[id] = d4; else ss[j][node] = d4; }
        }
        __syncthreads();

        // ---- coefficients: warp0 = ally softmax, warp1 = opp softmax, warp2 = self mask ----
        if (w == 2) {
            if (lane < 3) sc[lane][0] = mask_val(mask, kind, lane * (BB * NN) + b * NN);
        } else if (w < 2) {
            const int NE  = (w == 0) ? NAE : NOE;
            const int NPJ = (w == 0) ? 15 : 16;
            const int nb  = (w == 0) ? 1 : 16;
            // per-type-row factor: a_j = max_i p[i,j], E_j = sum_i exp(p[i,j]-a_j)
            float aj = -1e30f, Ej = 0.f;
            if (lane < 3) {
                float p0 = sp[lane], p1 = sp[3 + lane], p2 = sp[6 + lane];
                aj = fmaxf(p0, fmaxf(p1, p2));
                Ej = __expf(p0 - aj) + __expf(p1 - aj) + __expf(p2 - aj);
            }
            int k0 = lane;
            int k1 = lane + 32; bool act1 = (k1 < NE); int k1c = act1 ? k1 : 0;
            int j0 = k0 / NPJ, node0 = nb + (k0 % NPJ);
            int j1 = k1c / NPJ, node1 = nb + (k1c % NPJ);
            float aj0 = __shfl_sync(0xffffffffu, aj, j0);
            float Ej0 = __shfl_sync(0xffffffffu, Ej, j0);
            float aj1 = __shfl_sync(0xffffffffu, aj, j1);
            float Ej1 = __shfl_sync(0xffffffffu, Ej, j1);
            bool v0 = (mask_val(mask, kind, j0 * (BB * NN) + b * NN + node0) == 0.f);
            bool v1 = act1 && (mask_val(mask, kind, j1 * (BB * NN) + b * NN + node1) == 0.f);
            float val0 = aj0 + ss[j0][node0];
            float val1 = aj1 + ss[j1][node1];
            float cand = fmaxf(v0 ? val0 : -1e30f, v1 ? val1 : -1e30f);
#pragma unroll
            for (int o = 16; o; o >>= 1) cand = fmaxf(cand, __shfl_xor_sync(0xffffffffu, cand, o));
            float r0 = v0 ? Ej0 * __expf(val0 - cand) : 0.f;
            float r1 = v1 ? Ej1 * __expf(val1 - cand) : 0.f;
            float Z = r0 + r1;
#pragma unroll
            for (int o = 16; o; o >>= 1) Z += __shfl_xor_sync(0xffffffffu, Z, o);
            float inv = (Z > 0.f) ? 1.f / Z : 0.f;   // all-masked => zeros (matches reference)
            sc[j0][node0] = r0 * inv;
            if (act1) sc[j1][node1] = r1 * inv;
        }
        __syncthreads();

        // ---- fold: z[t][d] = sum_node c[t][node] * h[node][d]  (conflict-free: lanes span d) ----
        for (int o = tid; o < 384; o += 256) {
            int t = o >> 7, d = o & 127;
            float acc = 0.f;
#pragma unroll
            for (int node = 0; node < 32; node++) acc += sc[t][node] * hb[node * 128 + d];
            g_z[(size_t)b * 384 + o] = acc;
        }
        __syncthreads();
    }
}

// ---------------- output GEMM: out = elu(z @ Wcat), packed f32x2 FMA ----------------
__device__ __forceinline__ unsigned long long packf2(float lo, float hi) {
    unsigned long long r;
    asm("mov.b64 %0, {%1, %2};" : "=l"(r) : "f"(lo), "f"(hi));
    return r;
}
__device__ __forceinline__ void ffma2(unsigned long long& acc, unsigned long long a, unsigned long long b) {
    asm("fma.rn.f32x2 %0, %1, %2, %0;" : "+l"(acc) : "l"(a), "l"(b));
}
__device__ __forceinline__ float2 unpackf2(unsigned long long v) {
    float lo, hi;
    asm("mov.b64 {%0, %1}, %2;" : "=f"(lo), "=f"(hi) : "l"(v));
    return make_float2(lo, hi);
}

__global__ void __launch_bounds__(256) out_kernel(const float* __restrict__ W,
                                                  float* __restrict__ out) {
    // z tile for 32 batches, stored batch-PAIR interleaved so one LDS.64 yields a packed f32x2 operand
    __shared__ __align__(16) float szp[16 * 384 * 2];   // 48KB
    const int tid = threadIdx.x;
    const int hh = tid & 127, sub = tid >> 7;
    const size_t zoff = (size_t)blockIdx.x * (32 * 384);

    for (int base = tid * 4; base < 32 * 384; base += 1024) {
        float4 v = *(const float4*)&g_z[zoff + base];
        int bb = base / 384, o = base % 384;
        int p = bb >> 1, par = bb & 1;
        int so = (p * 384 + o) * 2 + par;
        szp[so] = v.x; szp[so + 2] = v.y; szp[so + 4] = v.z; szp[so + 6] = v.w;
    }
    __syncthreads();

    unsigned long long acc[8];
#pragma unroll
    for (int k = 0; k < 8; k++) acc[k] = 0ULL;

#pragma unroll 4
    for (int o = 0; o < 384; o += 2) {
        float w0 = W[o * 128 + hh];
        float w1 = W[(o + 1) * 128 + hh];
        unsigned long long wp0 = packf2(w0, w0), wp1 = packf2(w1, w1);
#pragma unroll
        for (int k = 0; k < 8; k++) {
            int p = sub + 2 * k;
            longlong2 zz = *(const longlong2*)&szp[(p * 384 + o) * 2];
            ffma2(acc[k], (unsigned long long)zz.x, wp0);
            ffma2(acc[k], (unsigned long long)zz.y, wp1);
        }
    }

#pragma unroll
    for (int k = 0; k < 8; k++) {
        int p = sub + 2 * k;
        float2 v = unpackf2(acc[k]);
        int bg = blockIdx.x * 32 + 2 * p;
        out[(size_t)bg * 128 + hh]       = (v.x > 0.f) ? v.x : expm1f(v.x);
        out[(size_t)(bg + 1) * 128 + hh] = (v.y > 0.f) ? v.y : expm1f(v.y);
    }
}

// ---------------- launcher ----------------
extern "C" void kernel_launch(void* const* d_in, const int* in_sizes, int n_in,
                              void* d_out, int out_size) {
    // Locate inputs by element count (robust to how scalar args are passed).
    const float* h = nullptr;
    const void*  mask = nullptr;
    const float* W = nullptr;
    const float* a = nullptr;
    for (int i = 0; i < n_in; i++) {
        switch (in_sizes[i]) {
            case 33554432: h    = (const float*)d_in[i]; break;  // 8192*32*128
            case 786432:   mask = d_in[i];               break;  // 3*8192*32
            case 49152:    W    = (const float*)d_in[i]; break;  // 3*128*128
            case 768:      a    = (const float*)d_in[i]; break;  // 3*256*1
            default: break;
        }
    }
    // Fallback: positional binding per reference order (h, mask, [scalars], W, a),
    // skipping size-1 scalar inputs.
    if (!h || !mask || !W || !a) {
        int slot = 0;
        for (int i = 0; i < n_in; i++) {
            if (in_sizes[i] <= 1) continue;
            if      (slot == 0) h    = (const float*)d_in[i];
            else if (slot == 1) mask = d_in[i];
            else if (slot == 2) W    = (const float*)d_in[i];
            else if (slot == 3) a    = (const float*)d_in[i];
            slot++;
        }
    }
    float* out = (float*)d_out;

    detect_kernel<<<1, 256>>>((const unsigned*)mask);
    pre_kernel<<<6, 256>>>(W, a);
    main_kernel<<<512, 256>>>(h, mask);
    out_kernel<<<256, 256>>>(W, out);
}

// round 4
// speedup vs baseline: 1.1551x; 1.1551x over previous
#include <cuda_runtime.h>
#include <cstdint>
#include <cstddef>

#define BB   8192
#define NN   32
#define DD   128
#define NAE  45
#define NOE  48
#define GRID 256
#define BPC  32            // batches per CTA

// ---- dynamic smem layout (float offsets) ----
#define HH_OFF 0           // 3 x 4096 floats: tile ring (h tiles, then W chunks)
#define VU_OFF 12288       // 1152 floats: 9 v-vectors
#define Z_OFF  13440       // 16 pairs x 384 x 2 = 12288 floats
#define SP_OFF 25728       // 9 (+pad)
#define SS_OFF 25744       // 96: s[j*32+node]
#define SC_OFF 25840       // 96: c[t*32+node]
#define SMEM_FLOATS 25936
#define SMEM_BYTES (SMEM_FLOATS * 4)

// ---------------- device scratch ----------------
__device__ float g_vu[12 * 128];   // 9 v (W_i@a_top_j) then 3 u (W_j@a_bot_j)
__device__ int   g_mask_kind;      // 0=i32 1=u8 2=f32 3=i64 4=f64

__device__ __forceinline__ float mask_val(const void* m, int kind, int idx) {
    switch (kind) {
        case 0:  return (float)((const int*)m)[idx];
        case 1:  return (float)((const unsigned char*)m)[idx];
        case 2:  return ((const float*)m)[idx];
        case 3:  return ((const long long*)m)[idx] ? 1.f : 0.f;
        default: return (((const double*)m)[idx] != 0.0) ? 1.f : 0.f;
    }
}

// ---------------- prep: W@a precompute (blocks 0-5) + mask detect (block 6) ----------------
__global__ void prep_kernel(const float* __restrict__ W, const float* __restrict__ a,
                            const unsigned* __restrict__ m) {
    int tid = threadIdx.x;
    if (blockIdx.x == 6) {
        bool okI = true, okF = true, okD = true, oddNZ = false;
        for (int i = tid * 8; i < tid * 8 + 8; i++) {
            unsigned w = m[i];
            if (w && w != 1u)          okI = false;
            if (w && w != 0x3F800000u) okF = false;
            if (i & 1) { if (w) oddNZ = true; if (w && w != 0x3FF00000u) okD = false; }
            else       { if (w) okD = false; }
        }
        int aI = __syncthreads_and((int)okI);
        int aF = __syncthreads_and((int)okF);
        int aD = __syncthreads_and((int)okD);
        int oN = __syncthreads_or((int)oddNZ);
        if (tid == 0) {
            int k;
            if (aI)      k = oN ? 0 : 3;
            else if (aF) k = 2;
            else if (aD) k = 4;
            else         k = 1;
            g_mask_kind = k;
        }
        return;
    }
    int o = blockIdx.x * 256 + tid;
    int vec = o >> 7, d = o & 127;
    const float* wrow;
    const float* av;
    if (vec < 9) { int i = vec / 3, j = vec % 3; wrow = W + i * 16384 + d * 128; av = a + j * 256; }
    else         { int j = vec - 9;              wrow = W + j * 16384 + d * 128; av = a + j * 256 + 128; }
    float s = 0.f;
#pragma unroll 8
    for (int hh = 0; hh < 128; hh++) s += wrow[hh] * av[hh];
    g_vu[o] = s;
}

// ---------------- f32x2 helpers ----------------
__device__ __forceinline__ unsigned long long packf2(float lo, float hi) {
    unsigned long long r;
    asm("mov.b64 %0, {%1, %2};" : "=l"(r) : "f"(lo), "f"(hi));
    return r;
}
__device__ __forceinline__ void ffma2(unsigned long long& acc, unsigned long long a, unsigned long long b) {
    asm("fma.rn.f32x2 %0, %1, %2, %0;" : "+l"(acc) : "l"(a), "l"(b));
}
__device__ __forceinline__ float2 unpackf2(unsigned long long v) {
    float lo, hi;
    asm("mov.b64 {%0, %1}, %2;" : "=f"(lo), "=f"(hi) : "l"(v));
    return make_float2(lo, hi);
}
__device__ __forceinline__ float dot4(float4 a, float4 b) {
    return a.x * b.x + a.y * b.y + a.z * b.z + a.w * b.w;
}

// ---------------- fused: stream h -> coeffs -> z -> GEMM(+ELU) ----------------
__global__ void __launch_bounds__(256) fused_kernel(const float* __restrict__ h,
                                                    const void* __restrict__ mask,
                                                    const float* __restrict__ W,
                                                    float* __restrict__ out) {
    extern __shared__ float sm[];
    float* svu = sm + VU_OFF;
    float* sz  = sm + Z_OFF;
    float* sp  = sm + SP_OFF;
    float* ss  = sm + SS_OFF;
    float* sc  = sm + SC_OFF;

    const int tid = threadIdx.x, lane = tid & 31, w = tid >> 5;
    const int kind = g_mask_kind;
    const int b0 = blockIdx.x * BPC;
    const unsigned smem_hh = (unsigned)__cvta_generic_to_shared(sm + HH_OFF);

    auto prefetch16k = [&](const float* src, int buf) {
        unsigned dst = smem_hh + (unsigned)buf * 16384u;
#pragma unroll
        for (int k = 0; k < 4; k++) {
            int idx = tid + k * 256;
            asm volatile("cp.async.cg.shared.global [%0], [%1], 16;"
                         :: "r"(dst + idx * 16), "l"((const char*)src + idx * 16));
        }
    };

    // prologue: 2 tiles in flight + v-vectors to smem, u-vectors to registers
    prefetch16k(h + (size_t)b0 * 4096, 0);
    asm volatile("cp.async.commit_group;");
    prefetch16k(h + (size_t)(b0 + 1) * 4096, 1);
    asm volatile("cp.async.commit_group;");
    for (int i2 = tid; i2 < 1152; i2 += 256) svu[i2] = g_vu[i2];
    float4 u0 = *(const float4*)&g_vu[1152 + lane * 4];
    float4 u1 = *(const float4*)&g_vu[1280 + lane * 4];
    float4 u2 = *(const float4*)&g_vu[1408 + lane * 4];

    // ================= streaming phase =================
    for (int it = 0; it < BPC; it++) {
        const int b = b0 + it;
        asm volatile("cp.async.wait_group 1;");
        __syncthreads();                      // tile it ready; fold(it-1) complete
        if (it + 2 < BPC) prefetch16k(h + (size_t)(b + 2) * 4096, (it + 2) % 3);
        asm volatile("cp.async.commit_group;");

        const float*  hb  = sm + HH_OFF + (it % 3) * 4096;
        const float4* hb4 = (const float4*)hb;
        const float4* vu4 = (const float4*)svu;

        // ---- dots: 34 units over 8 warps. u<31: row u+1 x {u0,u1,u2}; u>=31: row0 x v[3q..3q+2]
#pragma unroll
        for (int k = 0; k < 5; k++) {
            int u = w + 8 * k;
            if (u < 34) {
                float d0, d1, d2;
                int q = 0;
                if (u < 31) {
                    float4 hv = hb4[(u + 1) * 32 + lane];
                    d0 = dot4(hv, u0); d1 = dot4(hv, u1); d2 = dot4(hv, u2);
                } else {
                    q = u - 31;
                    float4 hv = hb4[lane];
                    d0 = dot4(hv, vu4[(3 * q + 0) * 32 + lane]);
                    d1 = dot4(hv, vu4[(3 * q + 1) * 32 + lane]);
                    d2 = dot4(hv, vu4[(3 * q + 2) * 32 + lane]);
                }
#pragma unroll
                for (int o = 16; o; o >>= 1) {
                    d0 += __shfl_xor_sync(0xffffffffu, d0, o);
                    d1 += __shfl_xor_sync(0xffffffffu, d1, o);
                    d2 += __shfl_xor_sync(0xffffffffu, d2, o);
                }
                if (lane == 0) {
                    if (u < 31) { int row = u + 1; ss[row] = d0; ss[32 + row] = d1; ss[64 + row] = d2; }
                    else        { sp[3 * q] = d0; sp[3 * q + 1] = d1; sp[3 * q + 2] = d2; }
                }
            }
        }
        __syncthreads();

        // ---- coefficients: warp0 ally softmax, warp1 opp softmax, warp2 self mask
        if (w == 2) {
            if (lane < 3) sc[lane * 32] = mask_val(mask, kind, lane * (BB * NN) + b * NN);
        } else if (w < 2) {
            const int NE  = (w == 0) ? NAE : NOE;
            const int NPJ = (w == 0) ? 15 : 16;
            const int nb  = (w == 0) ? 1 : 16;
            float aj = -1e30f, Ej = 0.f;
            if (lane < 3) {
                float p0 = sp[lane], p1 = sp[3 + lane], p2 = sp[6 + lane];
                aj = fmaxf(p0, fmaxf(p1, p2));
                Ej = __expf(p0 - aj) + __expf(p1 - aj) + __expf(p2 - aj);
            }
            int k0 = lane;
            int k1 = lane + 32; bool act1 = (k1 < NE); int k1c = act1 ? k1 : 0;
            int j0 = k0 / NPJ, node0 = nb + (k0 % NPJ);
            int j1 = k1c / NPJ, node1 = nb + (k1c % NPJ);
            float aj0 = __shfl_sync(0xffffffffu, aj, j0);
            float Ej0 = __shfl_sync(0xffffffffu, Ej, j0);
            float aj1 = __shfl_sync(0xffffffffu, aj, j1);
            float Ej1 = __shfl_sync(0xffffffffu, Ej, j1);
            bool v0 = (mask_val(mask, kind, j0 * (BB * NN) + b * NN + node0) == 0.f);
            bool v1 = act1 && (mask_val(mask, kind, j1 * (BB * NN) + b * NN + node1) == 0.f);
            float val0 = aj0 + ss[j0 * 32 + node0];
            float val1 = aj1 + ss[j1 * 32 + node1];
            float cand = fmaxf(v0 ? val0 : -1e30f, v1 ? val1 : -1e30f);
#pragma unroll
            for (int o = 16; o; o >>= 1) cand = fmaxf(cand, __shfl_xor_sync(0xffffffffu, cand, o));
            float r0 = v0 ? Ej0 * __expf(val0 - cand) : 0.f;
            float r1 = v1 ? Ej1 * __expf(val1 - cand) : 0.f;
            float Z = r0 + r1;
#pragma unroll
            for (int o = 16; o; o >>= 1) Z += __shfl_xor_sync(0xffffffffu, Z, o);
            float inv = (Z > 0.f) ? 1.f / Z : 0.f;
            sc[j0 * 32 + node0] = r0 * inv;
            if (act1) sc[j1 * 32 + node1] = r1 * inv;
        }
        __syncthreads();

        // ---- fold into pair-interleaved z: sz[(p*384+o)*2+par]
        const int p = it >> 1, par = it & 1;
        {
            int o = tid, t = o >> 7, d = o & 127;
            float acc = 0.f;
#pragma unroll
            for (int node = 0; node < 32; node++) acc += sc[t * 32 + node] * hb[node * 128 + d];
            sz[(p * 384 + o) * 2 + par] = acc;
        }
        if (tid < 128) {
            int o = 256 + tid, d = tid;
            float acc = 0.f;
#pragma unroll
            for (int node = 0; node < 32; node++) acc += sc[2 * 32 + node] * hb[node * 128 + d];
            sz[(p * 384 + o) * 2 + par] = acc;
        }
    }

    // ================= GEMM phase: out = elu(z @ Wcat) =================
    __syncthreads();                          // fold(31) done before W overwrites ring
    prefetch16k(W, 0);
    asm volatile("cp.async.commit_group;");
    prefetch16k(W + 4096, 1);
    asm volatile("cp.async.commit_group;");

    const int hh = tid & 127, sub = tid >> 7;
    unsigned long long acc[8];
#pragma unroll
    for (int k = 0; k < 8; k++) acc[k] = 0ULL;

    for (int c = 0; c < 12; c++) {            // 12 chunks x 32 W rows
        asm volatile("cp.async.wait_group 1;");
        __syncthreads();
        if (c + 2 < 12) prefetch16k(W + (size_t)(c + 2) * 4096, (c + 2) % 3);
        asm volatile("cp.async.commit_group;");
        const float* sW = sm + HH_OFF + (c % 3) * 4096;

#pragma unroll
        for (int oo = 0; oo < 32; oo += 2) {
            float w0 = sW[oo * 128 + hh];
            float w1 = sW[(oo + 1) * 128 + hh];
            unsigned long long wp0 = packf2(w0, w0), wp1 = packf2(w1, w1);
            int ob = c * 32 + oo;
#pragma unroll
            for (int k = 0; k < 8; k++) {
                int p = sub + 2 * k;
                ulonglong2 zz = *(const ulonglong2*)&sz[(p * 384 + ob) * 2];
                ffma2(acc[k], zz.x, wp0);
                ffma2(acc[k], zz.y, wp1);
            }
        }
    }

#pragma unroll
    for (int k = 0; k < 8; k++) {
        int p = sub + 2 * k;
        float2 v = unpackf2(acc[k]);
        int bg = b0 + 2 * p;
        out[(size_t)bg * 128 + hh]       = (v.x > 0.f) ? v.x : expm1f(v.x);
        out[(size_t)(bg + 1) * 128 + hh] = (v.y > 0.f) ? v.y : expm1f(v.y);
    }
}

// ---------------- launcher ----------------
extern "C" void kernel_launch(void* const* d_in, const int* in_sizes, int n_in,
                              void* d_out, int out_size) {
    const float* h = nullptr;
    const void*  mask = nullptr;
    const float* W = nullptr;
    const float* a = nullptr;
    for (int i = 0; i < n_in; i++) {
        switch (in_sizes[i]) {
            case 33554432: h    = (const float*)d_in[i]; break;
            case 786432:   mask = d_in[i];               break;
            case 49152:    W    = (const float*)d_in[i]; break;
            case 768:      a    = (const float*)d_in[i]; break;
            default: break;
        }
    }
    if (!h || !mask || !W || !a) {
        int slot = 0;
        for (int i = 0; i < n_in; i++) {
            if (in_sizes[i] <= 1) continue;
            if      (slot == 0) h    = (const float*)d_in[i];
            else if (slot == 1) mask = d_in[i];
            else if (slot == 2) W    = (const float*)d_in[i];
            else if (slot == 3) a    = (const float*)d_in[i];
            slot++;
        }
    }
    float* out = (float*)d_out;

    cudaFuncSetAttribute(fused_kernel, cudaFuncAttributeMaxDynamicSharedMemorySize, SMEM_BYTES);

    prep_kernel<<<7, 256>>>(W, a, (const unsigned*)mask);
    fused_kernel<<<GRID, 256, SMEM_BYTES>>>(h, mask, W, out);
}